// round 3
// baseline (speedup 1.0000x reference)
#include <cuda_runtime.h>
#include <math.h>

// ---------------- problem constants ----------------
#define B_     2
#define LQ_    21760
#define M_     (B_ * LQ_)      // 43520
#define C_     256
#define NHEAD_ 8
#define DK_    32
#define NS_    4
#define KPT_   4
#define NL_    6
#define FF_    1024

__device__ __constant__ int d_scH[4]   = {128, 64, 32, 16};
__device__ __constant__ int d_scW[4]   = {128, 64, 32, 16};
__device__ __constant__ int d_scSt[4]  = {0, 16384, 20480, 21504};

// ---------------- scratch (device globals; no allocation) ----------------
__device__ float g_x   [(size_t)M_ * C_];   // running activation
__device__ float g_xp  [(size_t)M_ * C_];   // x + pos
__device__ float g_v   [(size_t)M_ * C_];   // value proj
__device__ float g_off [(size_t)M_ * 256];  // sampling offsets (NHEAD*NS*K*2 = 256)
__device__ float g_att [(size_t)M_ * 128];  // attention weights (NHEAD*NS*K = 128)
__device__ float g_samp[(size_t)M_ * C_];   // sampled/weighted value
__device__ float g_a   [(size_t)M_ * C_];   // attn output proj
__device__ float g_h   [(size_t)M_ * FF_];  // FFN hidden
__device__ float g_f   [(size_t)M_ * C_];   // FFN out / att logits scratch

// ---------------- elementwise add (xp = x + pos) ----------------
__global__ void add_kernel(const float* __restrict__ a, const float* __restrict__ b,
                           float* __restrict__ out, int n4) {
    int i = blockIdx.x * blockDim.x + threadIdx.x;
    if (i >= n4) return;
    float4 va = ((const float4*)a)[i];
    float4 vb = ((const float4*)b)[i];
    va.x += vb.x; va.y += vb.y; va.z += vb.z; va.w += vb.w;
    ((float4*)out)[i] = va;
}

// ---------------- SGEMM: C[M,N] = A[M,K] @ W[K,N] + bias, optional relu ----
// 128x128 tile, BK=8, 256 threads, 8x8 per thread.
#define BM 128
#define BN 128
#define BK 8
__global__ __launch_bounds__(256, 2)
void sgemm_kernel(const float* __restrict__ A, const float* __restrict__ W,
                  const float* __restrict__ bias, float* __restrict__ Cout,
                  int N, int Kd, int relu) {
    __shared__ float As[BK][BM];
    __shared__ float Bs[BK][BN];
    const int tid = threadIdx.x;
    const int bx = blockIdx.x;   // N tile
    const int by = blockIdx.y;   // M tile

    const int aRow = tid >> 1;          // 0..127
    const int aCol = (tid & 1) * 4;     // 0 or 4
    const int bRow = tid >> 5;          // 0..7
    const int bCol = (tid & 31) * 4;    // 0..124

    const float* Ablk = A + (size_t)(by * BM) * Kd;
    const float* Wblk = W + bx * BN;

    const int tx = tid & 15;
    const int ty = tid >> 4;

    float acc[8][8];
#pragma unroll
    for (int i = 0; i < 8; i++)
#pragma unroll
        for (int j = 0; j < 8; j++) acc[i][j] = 0.f;

    for (int k0 = 0; k0 < Kd; k0 += BK) {
        float4 av = *(const float4*)(Ablk + (size_t)aRow * Kd + k0 + aCol);
        As[aCol + 0][aRow] = av.x;
        As[aCol + 1][aRow] = av.y;
        As[aCol + 2][aRow] = av.z;
        As[aCol + 3][aRow] = av.w;
        float4 bv = *(const float4*)(Wblk + (size_t)(k0 + bRow) * N + bCol);
        *(float4*)&Bs[bRow][bCol] = bv;
        __syncthreads();
#pragma unroll
        for (int kk = 0; kk < BK; kk++) {
            float a[8], b[8];
            *(float4*)&a[0] = *(const float4*)&As[kk][ty * 8];
            *(float4*)&a[4] = *(const float4*)&As[kk][ty * 8 + 4];
            *(float4*)&b[0] = *(const float4*)&Bs[kk][tx * 8];
            *(float4*)&b[4] = *(const float4*)&Bs[kk][tx * 8 + 4];
#pragma unroll
            for (int i = 0; i < 8; i++)
#pragma unroll
                for (int j = 0; j < 8; j++) acc[i][j] = fmaf(a[i], b[j], acc[i][j]);
        }
        __syncthreads();
    }

    // epilogue: bias (+relu), vectorized stores
    const int colBase = bx * BN + tx * 8;
    float bsv[8];
    *(float4*)&bsv[0] = *(const float4*)(bias + colBase);
    *(float4*)&bsv[4] = *(const float4*)(bias + colBase + 4);
#pragma unroll
    for (int i = 0; i < 8; i++) {
        const int row = by * BM + ty * 8 + i;
        float out[8];
#pragma unroll
        for (int j = 0; j < 8; j++) {
            float vv = acc[i][j] + bsv[j];
            if (relu) vv = fmaxf(vv, 0.f);
            out[j] = vv;
        }
        *(float4*)(Cout + (size_t)row * N + colBase)     = *(float4*)&out[0];
        *(float4*)(Cout + (size_t)row * N + colBase + 4) = *(float4*)&out[4];
    }
}

// ---------------- softmax over 16 per (row, head) ----------------
__global__ void softmax16_kernel(const float* __restrict__ logits,
                                 float* __restrict__ att, int total) {
    int t = blockIdx.x * blockDim.x + threadIdx.x;   // one per (row*8 + head)
    if (t >= total) return;
    const float* p = logits + (size_t)t * 16;
    float v[16];
    float mx = -1e30f;
#pragma unroll
    for (int i = 0; i < 16; i++) { v[i] = p[i]; mx = fmaxf(mx, v[i]); }
    float s = 0.f;
#pragma unroll
    for (int i = 0; i < 16; i++) { v[i] = __expf(v[i] - mx); s += v[i]; }
    float inv = 1.f / s;
    float* q = att + (size_t)t * 16;
#pragma unroll
    for (int i = 0; i < 16; i++) q[i] = v[i] * inv;
}

// ---------------- deformable sampling ----------------
// grid = M rows; block = 256 (warp per head, lane = channel)
__global__ void deform_sample_kernel(const float* __restrict__ v,
                                     const float* __restrict__ off,
                                     const float* __restrict__ att,
                                     const float* __restrict__ ref,
                                     float* __restrict__ out) {
    const int q = blockIdx.x;          // 0..M-1 (global row = b*LQ + qq)
    const int h = threadIdx.x >> 5;
    const int d = threadIdx.x & 31;
    const int b = q / LQ_;

    const float rx = ref[(size_t)q * 2 + 0];
    const float ry = ref[(size_t)q * 2 + 1];
    const float* offq = off + (size_t)q * 256 + h * 32;
    const float* attq = att + (size_t)q * 128 + h * 16;

    float acc = 0.f;
#pragma unroll
    for (int l = 0; l < 4; l++) {
        const int Hl = d_scH[l], Wl = d_scW[l], st = d_scSt[l];
        const float invW = 1.f / (float)Wl, invH = 1.f / (float)Hl;
        const float Wm1 = (float)(Wl - 1), Hm1 = (float)(Hl - 1);
        const float* vl = v + ((size_t)(b * LQ_ + st)) * C_ + h * 32 + d;
#pragma unroll
        for (int k = 0; k < 4; k++) {
            const float ox = offq[l * 8 + k * 2 + 0];
            const float oy = offq[l * 8 + k * 2 + 1];
            const float w  = attq[l * 4 + k];
            float x = (rx + ox * invW) * Wm1;
            float y = (ry + oy * invH) * Hm1;
            x = fminf(fmaxf(x, 0.f), Wm1);
            y = fminf(fmaxf(y, 0.f), Hm1);
            const float x0f = floorf(x), y0f = floorf(y);
            const int x0 = (int)x0f, y0 = (int)y0f;
            const int x1 = min(x0 + 1, Wl - 1), y1 = min(y0 + 1, Hl - 1);
            const float wx = x - x0f, wy = y - y0f;
            const float v00 = vl[(size_t)(y0 * Wl + x0) * C_];
            const float v01 = vl[(size_t)(y0 * Wl + x1) * C_];
            const float v10 = vl[(size_t)(y1 * Wl + x0) * C_];
            const float v11 = vl[(size_t)(y1 * Wl + x1) * C_];
            const float top = v00 + wx * (v01 - v00);
            const float bot = v10 + wx * (v11 - v10);
            acc = fmaf(w, top + wy * (bot - top), acc);
        }
    }
    out[(size_t)q * C_ + h * 32 + d] = acc;
}

// ---------------- fused residual + layernorm ----------------
// out = LN(a + b) * gamma + beta ; row of 256; warp per row, 8 rows/block
__global__ void ln_fused_kernel(const float* __restrict__ a, const float* __restrict__ b,
                                const float* __restrict__ gamma, const float* __restrict__ beta,
                                float* __restrict__ out) {
    const int row = blockIdx.x * 8 + (threadIdx.x >> 5);
    const int lane = threadIdx.x & 31;
    const float* pa = a + (size_t)row * C_;
    const float* pb = b + (size_t)row * C_;

    float vals[8];
    float s = 0.f;
#pragma unroll
    for (int i = 0; i < 8; i++) {
        const int c = lane + i * 32;
        vals[i] = pa[c] + pb[c];
        s += vals[i];
    }
#pragma unroll
    for (int o = 16; o > 0; o >>= 1) s += __shfl_xor_sync(0xffffffffu, s, o);
    const float mean = s * (1.f / 256.f);
    float vs = 0.f;
#pragma unroll
    for (int i = 0; i < 8; i++) {
        const float dlt = vals[i] - mean;
        vs += dlt * dlt;
    }
#pragma unroll
    for (int o = 16; o > 0; o >>= 1) vs += __shfl_xor_sync(0xffffffffu, vs, o);
    const float rstd = rsqrtf(vs * (1.f / 256.f) + 1e-5f);
#pragma unroll
    for (int i = 0; i < 8; i++) {
        const int c = lane + i * 32;
        out[(size_t)row * C_ + c] = (vals[i] - mean) * rstd * gamma[c] + beta[c];
    }
}

// ---------------- launch ----------------
extern "C" void kernel_launch(void* const* d_in, const int* in_sizes, int n_in,
                              void* d_out, int out_size) {
    const float* src  = (const float*)d_in[0];
    const float* pos  = (const float*)d_in[1];
    const float* ref  = (const float*)d_in[2];
    const float* Woff = (const float*)d_in[3];
    const float* boff = (const float*)d_in[4];
    const float* Wat  = (const float*)d_in[5];
    const float* bat  = (const float*)d_in[6];
    const float* Wv   = (const float*)d_in[7];
    const float* bv   = (const float*)d_in[8];
    const float* Wo   = (const float*)d_in[9];
    const float* bo   = (const float*)d_in[10];
    const float* W1   = (const float*)d_in[11];
    const float* b1   = (const float*)d_in[12];
    const float* W2   = (const float*)d_in[13];
    const float* b2   = (const float*)d_in[14];
    const float* n1s  = (const float*)d_in[15];
    const float* n1b  = (const float*)d_in[16];
    const float* n2s  = (const float*)d_in[17];
    const float* n2b  = (const float*)d_in[18];
    float* outp = (float*)d_out;

    float *x, *xp, *v, *off, *att, *samp, *a, *hbuf, *fbuf;
    cudaGetSymbolAddress((void**)&x,    g_x);
    cudaGetSymbolAddress((void**)&xp,   g_xp);
    cudaGetSymbolAddress((void**)&v,    g_v);
    cudaGetSymbolAddress((void**)&off,  g_off);
    cudaGetSymbolAddress((void**)&att,  g_att);
    cudaGetSymbolAddress((void**)&samp, g_samp);
    cudaGetSymbolAddress((void**)&a,    g_a);
    cudaGetSymbolAddress((void**)&hbuf, g_h);
    cudaGetSymbolAddress((void**)&fbuf, g_f);

    const int n4 = M_ * C_ / 4;
    const dim3 gemmN256(2, M_ / BM);
    const dim3 gemmN128(1, M_ / BM);
    const dim3 gemmN1024(8, M_ / BM);

    for (int i = 0; i < NL_; i++) {
        const float* xin = (i == 0) ? src : x;
        // xp = x + pos
        add_kernel<<<(n4 + 255) / 256, 256>>>(xin, pos, xp, n4);
        // v = xp @ Wv + bv
        sgemm_kernel<<<gemmN256, 256>>>(xp, Wv + (size_t)i * C_ * C_, bv + (size_t)i * C_, v, 256, C_, 0);
        // off = xp @ Woff + boff
        sgemm_kernel<<<gemmN256, 256>>>(xp, Woff + (size_t)i * C_ * 256, boff + (size_t)i * 256, off, 256, C_, 0);
        // att logits = xp @ Wat + bat (logits into fbuf scratch)
        sgemm_kernel<<<gemmN128, 256>>>(xp, Wat + (size_t)i * C_ * 128, bat + (size_t)i * 128, fbuf, 128, C_, 0);
        softmax16_kernel<<<(M_ * 8 + 255) / 256, 256>>>(fbuf, att, M_ * 8);
        // deformable sampling
        deform_sample_kernel<<<M_, 256>>>(v, off, att, ref, samp);
        // a = samp @ Wo + bo
        sgemm_kernel<<<gemmN256, 256>>>(samp, Wo + (size_t)i * C_ * C_, bo + (size_t)i * C_, a, 256, C_, 0);
        // x = LN(xp + a)
        ln_fused_kernel<<<M_ / 8, 256>>>(xp, a, n1s + (size_t)i * C_, n1b + (size_t)i * C_, x);
        // h = relu(x @ W1 + b1)
        sgemm_kernel<<<gemmN1024, 256>>>(x, W1 + (size_t)i * C_ * FF_, b1 + (size_t)i * FF_, hbuf, FF_, C_, 1);
        // f = h @ W2 + b2
        sgemm_kernel<<<gemmN256, 256>>>(hbuf, W2 + (size_t)i * FF_ * C_, b2 + (size_t)i * C_, fbuf, 256, FF_, 0);
        // x = LN(x + f)  (last layer writes straight to d_out)
        float* lnout = (i == NL_ - 1) ? outp : x;
        ln_fused_kernel<<<M_ / 8, 256>>>(x, fbuf, n2s + (size_t)i * C_, n2b + (size_t)i * C_, lnout);
    }
    (void)in_sizes; (void)n_in; (void)out_size;
}

// round 4
// speedup vs baseline: 2.3330x; 2.3330x over previous
#include <cuda_runtime.h>
#include <math.h>
#include <stdint.h>

// ---------------- problem constants ----------------
#define B_     2
#define LQ_    21760
#define M_     (B_ * LQ_)      // 43520
#define C_     256
#define NHEAD_ 8
#define DK_    32
#define NS_    4
#define KPT_   4
#define NL_    6
#define FF_    1024

__device__ __constant__ int d_scH[4]   = {128, 64, 32, 16};
__device__ __constant__ int d_scW[4]   = {128, 64, 32, 16};
__device__ __constant__ int d_scSt[4]  = {0, 16384, 20480, 21504};

// ---------------- scratch (device globals; no allocation) ----------------
__device__ float g_x   [(size_t)M_ * C_];
__device__ float g_xp  [(size_t)M_ * C_];
__device__ float g_v   [(size_t)M_ * C_];
__device__ float g_off [(size_t)M_ * 256];
__device__ float g_att [(size_t)M_ * 128];
__device__ float g_samp[(size_t)M_ * C_];
__device__ float g_a   [(size_t)M_ * C_];
__device__ float g_h   [(size_t)M_ * FF_];
__device__ float g_f   [(size_t)M_ * C_];

// ---------------- elementwise add (xp = x + pos) ----------------
__global__ void add_kernel(const float* __restrict__ a, const float* __restrict__ b,
                           float* __restrict__ out, int n4) {
    int i = blockIdx.x * blockDim.x + threadIdx.x;
    if (i >= n4) return;
    float4 va = ((const float4*)a)[i];
    float4 vb = ((const float4*)b)[i];
    va.x += vb.x; va.y += vb.y; va.z += vb.z; va.w += vb.w;
    ((float4*)out)[i] = va;
}

// ---------------- tf32 tensor-core GEMM ----------------
// C[M,N] = A[M,K] @ W[K,N] + bias, optional relu
// 128x128x32 tile, 256 threads (8 warps in 2x4), warp tile 64x32 via m16n8k8.
#define BM 128
#define BN 128
#define BK 32

__device__ __forceinline__ uint32_t f2tf32(float x) {
    uint32_t r;
    asm("cvt.rna.tf32.f32 %0, %1;" : "=r"(r) : "f"(x));
    return r;
}

__global__ __launch_bounds__(256, 2)
void tf32gemm_kernel(const float* __restrict__ A, const float* __restrict__ W,
                     const float* __restrict__ bias, float* __restrict__ Cout,
                     int N, int Kd, int relu) {
    __shared__ float As[BM][BK + 4];   // [128][36] — frag loads conflict-free
    __shared__ float Bs[BK][BN + 8];   // [32][136]

    const int tid  = threadIdx.x;
    const int warp = tid >> 5;
    const int lane = tid & 31;
    const int m0 = (warp >> 2) * 64;   // warp row offset within tile
    const int n0 = (warp & 3) * 32;    // warp col offset within tile
    const int bx = blockIdx.x, by = blockIdx.y;

    const int lr = tid >> 3;           // 0..31
    const int lc = (tid & 7) * 4;      // 0..28

    const float* Ag = A + (size_t)(by * BM) * Kd;
    const float* Wg = W + (size_t)bx * BN;

    float acc[4][4][4];
#pragma unroll
    for (int mi = 0; mi < 4; mi++)
#pragma unroll
        for (int nf = 0; nf < 4; nf++)
#pragma unroll
            for (int r = 0; r < 4; r++) acc[mi][nf][r] = 0.f;

    for (int k0 = 0; k0 < Kd; k0 += BK) {
        // load A tile 128x32: 4 passes of 32 rows, 8 lanes x float4 per row
#pragma unroll
        for (int p = 0; p < 4; p++) {
            const int row = p * 32 + lr;
            float4 v = *(const float4*)(Ag + (size_t)row * Kd + k0 + lc);
            As[row][lc + 0] = __uint_as_float(f2tf32(v.x));
            As[row][lc + 1] = __uint_as_float(f2tf32(v.y));
            As[row][lc + 2] = __uint_as_float(f2tf32(v.z));
            As[row][lc + 3] = __uint_as_float(f2tf32(v.w));
        }
        // load B tile 32x128: rows = lr, 4 col passes
#pragma unroll
        for (int p = 0; p < 4; p++) {
            const int col = p * 32 + lc;
            float4 v = *(const float4*)(Wg + (size_t)(k0 + lr) * N + col);
            Bs[lr][col + 0] = __uint_as_float(f2tf32(v.x));
            Bs[lr][col + 1] = __uint_as_float(f2tf32(v.y));
            Bs[lr][col + 2] = __uint_as_float(f2tf32(v.z));
            Bs[lr][col + 3] = __uint_as_float(f2tf32(v.w));
        }
        __syncthreads();

#pragma unroll
        for (int kk = 0; kk < BK; kk += 8) {
            uint32_t a[4][4];
            uint32_t b[4][2];
            const int ar = lane >> 2;       // 0..7
            const int ak = lane & 3;        // 0..3
#pragma unroll
            for (int mi = 0; mi < 4; mi++) {
                const int r = m0 + mi * 16 + ar;
                a[mi][0] = __float_as_uint(As[r    ][kk + ak    ]);
                a[mi][1] = __float_as_uint(As[r + 8][kk + ak    ]);
                a[mi][2] = __float_as_uint(As[r    ][kk + ak + 4]);
                a[mi][3] = __float_as_uint(As[r + 8][kk + ak + 4]);
            }
#pragma unroll
            for (int nf = 0; nf < 4; nf++) {
                const int c = n0 + nf * 8 + ar;
                b[nf][0] = __float_as_uint(Bs[kk + ak    ][c]);
                b[nf][1] = __float_as_uint(Bs[kk + ak + 4][c]);
            }
#pragma unroll
            for (int mi = 0; mi < 4; mi++)
#pragma unroll
                for (int nf = 0; nf < 4; nf++) {
                    asm volatile(
                        "mma.sync.aligned.m16n8k8.row.col.f32.tf32.tf32.f32 "
                        "{%0,%1,%2,%3}, {%4,%5,%6,%7}, {%8,%9}, {%0,%1,%2,%3};"
                        : "+f"(acc[mi][nf][0]), "+f"(acc[mi][nf][1]),
                          "+f"(acc[mi][nf][2]), "+f"(acc[mi][nf][3])
                        : "r"(a[mi][0]), "r"(a[mi][1]), "r"(a[mi][2]), "r"(a[mi][3]),
                          "r"(b[nf][0]), "r"(b[nf][1]));
                }
        }
        __syncthreads();
    }

    // epilogue: bias (+relu)
    const int gr = lane >> 2;           // 0..7
    const int gc = (lane & 3) * 2;      // 0,2,4,6
#pragma unroll
    for (int mi = 0; mi < 4; mi++) {
#pragma unroll
        for (int nf = 0; nf < 4; nf++) {
            const int col = bx * BN + n0 + nf * 8 + gc;
            const float b0 = bias[col], b1 = bias[col + 1];
            const int row0 = by * BM + m0 + mi * 16 + gr;

            float2 v0 = make_float2(acc[mi][nf][0] + b0, acc[mi][nf][1] + b1);
            float2 v1 = make_float2(acc[mi][nf][2] + b0, acc[mi][nf][3] + b1);
            if (relu) {
                v0.x = fmaxf(v0.x, 0.f); v0.y = fmaxf(v0.y, 0.f);
                v1.x = fmaxf(v1.x, 0.f); v1.y = fmaxf(v1.y, 0.f);
            }
            *(float2*)(Cout + (size_t)row0 * N + col)       = v0;
            *(float2*)(Cout + (size_t)(row0 + 8) * N + col) = v1;
        }
    }
}

// ---------------- softmax over 16 per (row, head) ----------------
__global__ void softmax16_kernel(const float* __restrict__ logits,
                                 float* __restrict__ att, int total) {
    int t = blockIdx.x * blockDim.x + threadIdx.x;
    if (t >= total) return;
    const float* p = logits + (size_t)t * 16;
    float v[16];
    float mx = -1e30f;
#pragma unroll
    for (int i = 0; i < 16; i++) { v[i] = p[i]; mx = fmaxf(mx, v[i]); }
    float s = 0.f;
#pragma unroll
    for (int i = 0; i < 16; i++) { v[i] = __expf(v[i] - mx); s += v[i]; }
    float inv = 1.f / s;
    float* q = att + (size_t)t * 16;
#pragma unroll
    for (int i = 0; i < 16; i++) q[i] = v[i] * inv;
}

// ---------------- deformable sampling ----------------
__global__ void deform_sample_kernel(const float* __restrict__ v,
                                     const float* __restrict__ off,
                                     const float* __restrict__ att,
                                     const float* __restrict__ ref,
                                     float* __restrict__ out) {
    const int q = blockIdx.x;
    const int h = threadIdx.x >> 5;
    const int d = threadIdx.x & 31;
    const int b = q / LQ_;

    const float rx = ref[(size_t)q * 2 + 0];
    const float ry = ref[(size_t)q * 2 + 1];
    const float* offq = off + (size_t)q * 256 + h * 32;
    const float* attq = att + (size_t)q * 128 + h * 16;

    float acc = 0.f;
#pragma unroll
    for (int l = 0; l < 4; l++) {
        const int Hl = d_scH[l], Wl = d_scW[l], st = d_scSt[l];
        const float invW = 1.f / (float)Wl, invH = 1.f / (float)Hl;
        const float Wm1 = (float)(Wl - 1), Hm1 = (float)(Hl - 1);
        const float* vl = v + ((size_t)(b * LQ_ + st)) * C_ + h * 32 + d;
#pragma unroll
        for (int k = 0; k < 4; k++) {
            const float ox = offq[l * 8 + k * 2 + 0];
            const float oy = offq[l * 8 + k * 2 + 1];
            const float w  = attq[l * 4 + k];
            float x = (rx + ox * invW) * Wm1;
            float y = (ry + oy * invH) * Hm1;
            x = fminf(fmaxf(x, 0.f), Wm1);
            y = fminf(fmaxf(y, 0.f), Hm1);
            const float x0f = floorf(x), y0f = floorf(y);
            const int x0 = (int)x0f, y0 = (int)y0f;
            const int x1 = min(x0 + 1, Wl - 1), y1 = min(y0 + 1, Hl - 1);
            const float wx = x - x0f, wy = y - y0f;
            const float v00 = vl[(size_t)(y0 * Wl + x0) * C_];
            const float v01 = vl[(size_t)(y0 * Wl + x1) * C_];
            const float v10 = vl[(size_t)(y1 * Wl + x0) * C_];
            const float v11 = vl[(size_t)(y1 * Wl + x1) * C_];
            const float top = v00 + wx * (v01 - v00);
            const float bot = v10 + wx * (v11 - v10);
            acc = fmaf(w, top + wy * (bot - top), acc);
        }
    }
    out[(size_t)q * C_ + h * 32 + d] = acc;
}

// ---------------- fused residual + layernorm ----------------
__global__ void ln_fused_kernel(const float* __restrict__ a, const float* __restrict__ b,
                                const float* __restrict__ gamma, const float* __restrict__ beta,
                                float* __restrict__ out) {
    const int row = blockIdx.x * 8 + (threadIdx.x >> 5);
    const int lane = threadIdx.x & 31;
    const float* pa = a + (size_t)row * C_;
    const float* pb = b + (size_t)row * C_;

    float vals[8];
    float s = 0.f;
#pragma unroll
    for (int i = 0; i < 8; i++) {
        const int c = lane + i * 32;
        vals[i] = pa[c] + pb[c];
        s += vals[i];
    }
#pragma unroll
    for (int o = 16; o > 0; o >>= 1) s += __shfl_xor_sync(0xffffffffu, s, o);
    const float mean = s * (1.f / 256.f);
    float vs = 0.f;
#pragma unroll
    for (int i = 0; i < 8; i++) {
        const float dlt = vals[i] - mean;
        vs += dlt * dlt;
    }
#pragma unroll
    for (int o = 16; o > 0; o >>= 1) vs += __shfl_xor_sync(0xffffffffu, vs, o);
    const float rstd = rsqrtf(vs * (1.f / 256.f) + 1e-5f);
#pragma unroll
    for (int i = 0; i < 8; i++) {
        const int c = lane + i * 32;
        out[(size_t)row * C_ + c] = (vals[i] - mean) * rstd * gamma[c] + beta[c];
    }
}

// ---------------- launch ----------------
extern "C" void kernel_launch(void* const* d_in, const int* in_sizes, int n_in,
                              void* d_out, int out_size) {
    const float* src  = (const float*)d_in[0];
    const float* pos  = (const float*)d_in[1];
    const float* ref  = (const float*)d_in[2];
    const float* Woff = (const float*)d_in[3];
    const float* boff = (const float*)d_in[4];
    const float* Wat  = (const float*)d_in[5];
    const float* bat  = (const float*)d_in[6];
    const float* Wv   = (const float*)d_in[7];
    const float* bv   = (const float*)d_in[8];
    const float* Wo   = (const float*)d_in[9];
    const float* bo   = (const float*)d_in[10];
    const float* W1   = (const float*)d_in[11];
    const float* b1   = (const float*)d_in[12];
    const float* W2   = (const float*)d_in[13];
    const float* b2   = (const float*)d_in[14];
    const float* n1s  = (const float*)d_in[15];
    const float* n1b  = (const float*)d_in[16];
    const float* n2s  = (const float*)d_in[17];
    const float* n2b  = (const float*)d_in[18];
    float* outp = (float*)d_out;

    float *x, *xp, *v, *off, *att, *samp, *a, *hbuf, *fbuf;
    cudaGetSymbolAddress((void**)&x,    g_x);
    cudaGetSymbolAddress((void**)&xp,   g_xp);
    cudaGetSymbolAddress((void**)&v,    g_v);
    cudaGetSymbolAddress((void**)&off,  g_off);
    cudaGetSymbolAddress((void**)&att,  g_att);
    cudaGetSymbolAddress((void**)&samp, g_samp);
    cudaGetSymbolAddress((void**)&a,    g_a);
    cudaGetSymbolAddress((void**)&hbuf, g_h);
    cudaGetSymbolAddress((void**)&fbuf, g_f);

    const int n4 = M_ * C_ / 4;
    const dim3 gemmN256(2, M_ / BM);
    const dim3 gemmN128(1, M_ / BM);
    const dim3 gemmN1024(8, M_ / BM);

    for (int i = 0; i < NL_; i++) {
        const float* xin = (i == 0) ? src : x;
        // xp = x + pos
        add_kernel<<<(n4 + 255) / 256, 256>>>(xin, pos, xp, n4);
        // v = xp @ Wv + bv
        tf32gemm_kernel<<<gemmN256, 256>>>(xp, Wv + (size_t)i * C_ * C_, bv + (size_t)i * C_, v, 256, C_, 0);
        // off = xp @ Woff + boff
        tf32gemm_kernel<<<gemmN256, 256>>>(xp, Woff + (size_t)i * C_ * 256, boff + (size_t)i * 256, off, 256, C_, 0);
        // att logits = xp @ Wat + bat
        tf32gemm_kernel<<<gemmN128, 256>>>(xp, Wat + (size_t)i * C_ * 128, bat + (size_t)i * 128, fbuf, 128, C_, 0);
        softmax16_kernel<<<(M_ * 8 + 255) / 256, 256>>>(fbuf, att, M_ * 8);
        // deformable sampling
        deform_sample_kernel<<<M_, 256>>>(v, off, att, ref, samp);
        // a = samp @ Wo + bo
        tf32gemm_kernel<<<gemmN256, 256>>>(samp, Wo + (size_t)i * C_ * C_, bo + (size_t)i * C_, a, 256, C_, 0);
        // x = LN(xp + a)
        ln_fused_kernel<<<M_ / 8, 256>>>(xp, a, n1s + (size_t)i * C_, n1b + (size_t)i * C_, x);
        // h = relu(x @ W1 + b1)
        tf32gemm_kernel<<<gemmN1024, 256>>>(x, W1 + (size_t)i * C_ * FF_, b1 + (size_t)i * FF_, hbuf, FF_, C_, 1);
        // f = h @ W2 + b2
        tf32gemm_kernel<<<gemmN256, 256>>>(hbuf, W2 + (size_t)i * FF_ * C_, b2 + (size_t)i * C_, fbuf, 256, FF_, 0);
        // x = LN(x + f)
        float* lnout = (i == NL_ - 1) ? outp : x;
        ln_fused_kernel<<<M_ / 8, 256>>>(x, fbuf, n2s + (size_t)i * C_, n2b + (size_t)i * C_, lnout);
    }
    (void)in_sizes; (void)n_in; (void)out_size;
}

// round 5
// speedup vs baseline: 2.5032x; 1.0730x over previous
#include <cuda_runtime.h>
#include <math.h>
#include <stdint.h>

// ---------------- problem constants ----------------
#define B_     2
#define LQ_    21760
#define M_     (B_ * LQ_)      // 43520
#define C_     256
#define NHEAD_ 8
#define NS_    4
#define NL_    6
#define FF_    1024
#define NQKV   640             // 256 (v) + 256 (off) + 128 (att logits)

__device__ __constant__ int d_scH[4]   = {128, 64, 32, 16};
__device__ __constant__ int d_scW[4]   = {128, 64, 32, 16};
__device__ __constant__ int d_scSt[4]  = {0, 16384, 20480, 21504};

// ---------------- scratch (device globals; no allocation) ----------------
__device__ float g_xp  [(size_t)M_ * C_];    // x + pos (exact, for residual)
__device__ float g_xpT [(size_t)M_ * C_];    // tf32-rounded xp (GEMM A input)
__device__ float g_qkv [(size_t)M_ * NQKV];  // fused v|off|logits output
__device__ float g_att [(size_t)M_ * 128];   // softmaxed attention
__device__ float g_samp[(size_t)M_ * C_];    // sampled value (tf32-rounded)
__device__ float g_a   [(size_t)M_ * C_];    // attn out proj (exact)
__device__ float g_x   [(size_t)M_ * C_];    // post-LN1 / post-LN2 (exact)
__device__ float g_xT  [(size_t)M_ * C_];    // tf32-rounded post-LN1
__device__ float g_h   [(size_t)M_ * FF_];   // FFN hidden (tf32-rounded)
__device__ float g_f   [(size_t)M_ * C_];    // FFN out (exact)
// pre-rounded / packed weights
__device__ float g_wq  [(size_t)NL_ * C_ * NQKV];
__device__ float g_bq  [(size_t)NL_ * NQKV];
__device__ float g_wo  [(size_t)NL_ * C_ * C_];
__device__ float g_w1  [(size_t)NL_ * C_ * FF_];
__device__ float g_w2  [(size_t)NL_ * FF_ * C_];

__device__ __forceinline__ uint32_t f2tf32(float x) {
    uint32_t r;
    asm("cvt.rna.tf32.f32 %0, %1;" : "=r"(r) : "f"(x));
    return r;
}
__device__ __forceinline__ float rndt(float x) { return __uint_as_float(f2tf32(x)); }

// ---------------- weight prep: round to tf32 grid ----------------
__global__ void round_kernel(const float* __restrict__ src, float* __restrict__ dst, int n4) {
    int i = blockIdx.x * blockDim.x + threadIdx.x;
    if (i >= n4) return;
    float4 v = ((const float4*)src)[i];
    v.x = rndt(v.x); v.y = rndt(v.y); v.z = rndt(v.z); v.w = rndt(v.w);
    ((float4*)dst)[i] = v;
}

// pack Wv|Woff|Wat (rounded) into [NL][C][640], and biases into [NL][640]
__global__ void pack_qkv_kernel(const float* __restrict__ Wv, const float* __restrict__ Woff,
                                const float* __restrict__ Wat,
                                const float* __restrict__ bv, const float* __restrict__ boff,
                                const float* __restrict__ bat,
                                float* __restrict__ wq, float* __restrict__ bq) {
    int idx = blockIdx.x * blockDim.x + threadIdx.x;   // over NL*C*NQKV
    const int total = NL_ * C_ * NQKV;
    if (idx < total) {
        const int c = idx % NQKV;
        const int k = (idx / NQKV) % C_;
        const int l = idx / (NQKV * C_);
        float v;
        if (c < 256)      v = Wv  [((size_t)l * C_ + k) * 256 + c];
        else if (c < 512) v = Woff[((size_t)l * C_ + k) * 256 + (c - 256)];
        else              v = Wat [((size_t)l * C_ + k) * 128 + (c - 512)];
        wq[idx] = rndt(v);
    }
    if (idx < NL_ * NQKV) {
        const int c = idx % NQKV;
        const int l = idx / NQKV;
        float v;
        if (c < 256)      v = bv  [l * 256 + c];
        else if (c < 512) v = boff[l * 256 + (c - 256)];
        else              v = bat [l * 128 + (c - 512)];
        bq[idx] = v;   // bias added in fp32 epilogue — no rounding
    }
}

// ---------------- add: xp = x + pos (exact) and rounded copy ----------------
__global__ void add_kernel(const float* __restrict__ a, const float* __restrict__ b,
                           float* __restrict__ out, float* __restrict__ outT, int n4) {
    int i = blockIdx.x * blockDim.x + threadIdx.x;
    if (i >= n4) return;
    float4 va = ((const float4*)a)[i];
    float4 vb = ((const float4*)b)[i];
    va.x += vb.x; va.y += vb.y; va.z += vb.z; va.w += vb.w;
    ((float4*)out)[i] = va;
    float4 vt = make_float4(rndt(va.x), rndt(va.y), rndt(va.z), rndt(va.w));
    ((float4*)outT)[i] = vt;
}

// ---------------- tf32 tensor-core GEMM, cp.async 2-stage ----------------
// Inputs A, W are PRE-ROUNDED to the tf32 grid. 128x128x32 tile, 256 thr.
#define BM 128
#define BN 128
#define BK 32
#define ASTRIDE 36
#define BSTRIDE 136
#define ASZ (BM * ASTRIDE)          // 4608 floats
#define BSZ (BK * BSTRIDE)          // 4352 floats
#define STAGEF (ASZ + BSZ)          // 8960 floats
#define GEMM_SMEM (2 * STAGEF * 4)  // 71680 bytes

__device__ __forceinline__ void cpa16(float* dst, const float* src) {
    uint32_t d = (uint32_t)__cvta_generic_to_shared(dst);
    asm volatile("cp.async.cg.shared.global [%0], [%1], 16;" :: "r"(d), "l"(src));
}

__global__ __launch_bounds__(256, 2)
void tf32gemm_kernel(const float* __restrict__ A, const float* __restrict__ W,
                     const float* __restrict__ bias, float* __restrict__ Cout,
                     int N, int Kd, int relu, int roundOut) {
    extern __shared__ __align__(16) float sm[];

    const int tid  = threadIdx.x;
    const int warp = tid >> 5;
    const int lane = tid & 31;
    const int m0 = (warp >> 2) * 64;
    const int n0 = (warp & 3) * 32;
    const int bx = blockIdx.x, by = blockIdx.y;

    const int lr = tid >> 3;           // 0..31
    const int lc = (tid & 7) * 4;      // 0,4,...,28

    const float* Ag = A + (size_t)(by * BM) * Kd;
    const float* Wg = W + (size_t)bx * BN;

    float acc[4][4][4];
#pragma unroll
    for (int mi = 0; mi < 4; mi++)
#pragma unroll
        for (int nf = 0; nf < 4; nf++)
#pragma unroll
            for (int r = 0; r < 4; r++) acc[mi][nf][r] = 0.f;

    const int NK = Kd / BK;

    // issue stage 0
    {
        float* as = sm;
        float* bs = sm + ASZ;
#pragma unroll
        for (int p = 0; p < 4; p++) {
            const int row = p * 32 + lr;
            cpa16(as + row * ASTRIDE + lc, Ag + (size_t)row * Kd + lc);
        }
#pragma unroll
        for (int p = 0; p < 4; p++) {
            const int col = p * 32 + lc;
            cpa16(bs + lr * BSTRIDE + col, Wg + (size_t)lr * N + col);
        }
        asm volatile("cp.async.commit_group;");
    }

    const int ar = lane >> 2;       // 0..7
    const int ak = lane & 3;        // 0..3

    for (int i = 0; i < NK; i++) {
        asm volatile("cp.async.wait_group 0;");
        __syncthreads();

        if (i + 1 < NK) {
            const int k0 = (i + 1) * BK;
            float* as = sm + ((i + 1) & 1) * STAGEF;
            float* bs = as + ASZ;
#pragma unroll
            for (int p = 0; p < 4; p++) {
                const int row = p * 32 + lr;
                cpa16(as + row * ASTRIDE + lc, Ag + (size_t)row * Kd + k0 + lc);
            }
#pragma unroll
            for (int p = 0; p < 4; p++) {
                const int col = p * 32 + lc;
                cpa16(bs + lr * BSTRIDE + col, Wg + (size_t)(k0 + lr) * N + col);
            }
            asm volatile("cp.async.commit_group;");
        }

        const float* as = sm + (i & 1) * STAGEF;
        const float* bs = as + ASZ;

#pragma unroll
        for (int kk = 0; kk < BK; kk += 8) {
            uint32_t a[4][4];
            uint32_t b[4][2];
#pragma unroll
            for (int mi = 0; mi < 4; mi++) {
                const int r = m0 + mi * 16 + ar;
                a[mi][0] = __float_as_uint(as[(r    ) * ASTRIDE + kk + ak    ]);
                a[mi][1] = __float_as_uint(as[(r + 8) * ASTRIDE + kk + ak    ]);
                a[mi][2] = __float_as_uint(as[(r    ) * ASTRIDE + kk + ak + 4]);
                a[mi][3] = __float_as_uint(as[(r + 8) * ASTRIDE + kk + ak + 4]);
            }
#pragma unroll
            for (int nf = 0; nf < 4; nf++) {
                const int c = n0 + nf * 8 + ar;
                b[nf][0] = __float_as_uint(bs[(kk + ak    ) * BSTRIDE + c]);
                b[nf][1] = __float_as_uint(bs[(kk + ak + 4) * BSTRIDE + c]);
            }
#pragma unroll
            for (int mi = 0; mi < 4; mi++)
#pragma unroll
                for (int nf = 0; nf < 4; nf++) {
                    asm volatile(
                        "mma.sync.aligned.m16n8k8.row.col.f32.tf32.tf32.f32 "
                        "{%0,%1,%2,%3}, {%4,%5,%6,%7}, {%8,%9}, {%0,%1,%2,%3};"
                        : "+f"(acc[mi][nf][0]), "+f"(acc[mi][nf][1]),
                          "+f"(acc[mi][nf][2]), "+f"(acc[mi][nf][3])
                        : "r"(a[mi][0]), "r"(a[mi][1]), "r"(a[mi][2]), "r"(a[mi][3]),
                          "r"(b[nf][0]), "r"(b[nf][1]));
                }
        }
        __syncthreads();
    }

    // epilogue: bias (+relu) (+round-to-tf32 for chained GEMM inputs)
    const int gr = lane >> 2;
    const int gc = (lane & 3) * 2;
#pragma unroll
    for (int mi = 0; mi < 4; mi++) {
#pragma unroll
        for (int nf = 0; nf < 4; nf++) {
            const int col = bx * BN + n0 + nf * 8 + gc;
            const float b0 = bias[col], b1 = bias[col + 1];
            const int row0 = by * BM + m0 + mi * 16 + gr;

            float2 v0 = make_float2(acc[mi][nf][0] + b0, acc[mi][nf][1] + b1);
            float2 v1 = make_float2(acc[mi][nf][2] + b0, acc[mi][nf][3] + b1);
            if (relu) {
                v0.x = fmaxf(v0.x, 0.f); v0.y = fmaxf(v0.y, 0.f);
                v1.x = fmaxf(v1.x, 0.f); v1.y = fmaxf(v1.y, 0.f);
            }
            if (roundOut) {
                v0.x = rndt(v0.x); v0.y = rndt(v0.y);
                v1.x = rndt(v1.x); v1.y = rndt(v1.y);
            }
            *(float2*)(Cout + (size_t)row0 * N + col)       = v0;
            *(float2*)(Cout + (size_t)(row0 + 8) * N + col) = v1;
        }
    }
}

// ---------------- softmax over 16 per (row, head), logits in g_qkv[.,512+] --
__global__ void softmax16_kernel(const float* __restrict__ qkv,
                                 float* __restrict__ att, int total) {
    int t = blockIdx.x * blockDim.x + threadIdx.x;   // (row*8 + head)
    if (t >= total) return;
    const int row = t >> 3, h = t & 7;
    const float* p = qkv + (size_t)row * NQKV + 512 + h * 16;
    float v[16];
    float mx = -1e30f;
#pragma unroll
    for (int i = 0; i < 16; i++) { v[i] = p[i]; mx = fmaxf(mx, v[i]); }
    float s = 0.f;
#pragma unroll
    for (int i = 0; i < 16; i++) { v[i] = __expf(v[i] - mx); s += v[i]; }
    float inv = 1.f / s;
    float* q = att + (size_t)t * 16;
#pragma unroll
    for (int i = 0; i < 16; i++) q[i] = v[i] * inv;
}

// ---------------- deformable sampling (v & off live inside g_qkv) ----------
__global__ void deform_sample_kernel(const float* __restrict__ qkv,
                                     const float* __restrict__ att,
                                     const float* __restrict__ ref,
                                     float* __restrict__ out) {
    const int q = blockIdx.x;
    const int h = threadIdx.x >> 5;
    const int d = threadIdx.x & 31;
    const int b = q / LQ_;

    const float rx = ref[(size_t)q * 2 + 0];
    const float ry = ref[(size_t)q * 2 + 1];
    const float* offq = qkv + (size_t)q * NQKV + 256 + h * 32;
    const float* attq = att + (size_t)q * 128 + h * 16;

    float acc = 0.f;
#pragma unroll
    for (int l = 0; l < 4; l++) {
        const int Hl = d_scH[l], Wl = d_scW[l], st = d_scSt[l];
        const float invW = 1.f / (float)Wl, invH = 1.f / (float)Hl;
        const float Wm1 = (float)(Wl - 1), Hm1 = (float)(Hl - 1);
        const float* vl = qkv + (size_t)(b * LQ_ + st) * NQKV + h * 32 + d;
#pragma unroll
        for (int k = 0; k < 4; k++) {
            const float ox = offq[l * 8 + k * 2 + 0];
            const float oy = offq[l * 8 + k * 2 + 1];
            const float w  = attq[l * 4 + k];
            float x = (rx + ox * invW) * Wm1;
            float y = (ry + oy * invH) * Hm1;
            x = fminf(fmaxf(x, 0.f), Wm1);
            y = fminf(fmaxf(y, 0.f), Hm1);
            const float x0f = floorf(x), y0f = floorf(y);
            const int x0 = (int)x0f, y0 = (int)y0f;
            const int x1 = min(x0 + 1, Wl - 1), y1 = min(y0 + 1, Hl - 1);
            const float wx = x - x0f, wy = y - y0f;
            const float v00 = vl[(size_t)(y0 * Wl + x0) * NQKV];
            const float v01 = vl[(size_t)(y0 * Wl + x1) * NQKV];
            const float v10 = vl[(size_t)(y1 * Wl + x0) * NQKV];
            const float v11 = vl[(size_t)(y1 * Wl + x1) * NQKV];
            const float top = v00 + wx * (v01 - v00);
            const float bot = v10 + wx * (v11 - v10);
            acc = fmaf(w, top + wy * (bot - top), acc);
        }
    }
    out[(size_t)q * C_ + h * 32 + d] = rndt(acc);   // feeds only Wo GEMM
}

// ---------------- fused residual + layernorm (optional rounded copy) -------
__global__ void ln_fused_kernel(const float* __restrict__ a, const float* __restrict__ b,
                                const float* __restrict__ gamma, const float* __restrict__ beta,
                                float* __restrict__ out, float* __restrict__ outT) {
    const int row = blockIdx.x * 8 + (threadIdx.x >> 5);
    const int lane = threadIdx.x & 31;
    const float* pa = a + (size_t)row * C_;
    const float* pb = b + (size_t)row * C_;

    float vals[8];
    float s = 0.f;
#pragma unroll
    for (int i = 0; i < 8; i++) {
        const int c = lane + i * 32;
        vals[i] = pa[c] + pb[c];
        s += vals[i];
    }
#pragma unroll
    for (int o = 16; o > 0; o >>= 1) s += __shfl_xor_sync(0xffffffffu, s, o);
    const float mean = s * (1.f / 256.f);
    float vs = 0.f;
#pragma unroll
    for (int i = 0; i < 8; i++) {
        const float dlt = vals[i] - mean;
        vs += dlt * dlt;
    }
#pragma unroll
    for (int o = 16; o > 0; o >>= 1) vs += __shfl_xor_sync(0xffffffffu, vs, o);
    const float rstd = rsqrtf(vs * (1.f / 256.f) + 1e-5f);
#pragma unroll
    for (int i = 0; i < 8; i++) {
        const int c = lane + i * 32;
        const float o = (vals[i] - mean) * rstd * gamma[c] + beta[c];
        out[(size_t)row * C_ + c] = o;
        if (outT) outT[(size_t)row * C_ + c] = rndt(o);
    }
}

// ---------------- launch ----------------
extern "C" void kernel_launch(void* const* d_in, const int* in_sizes, int n_in,
                              void* d_out, int out_size) {
    const float* src  = (const float*)d_in[0];
    const float* pos  = (const float*)d_in[1];
    const float* ref  = (const float*)d_in[2];
    const float* Woff = (const float*)d_in[3];
    const float* boff = (const float*)d_in[4];
    const float* Wat  = (const float*)d_in[5];
    const float* bat  = (const float*)d_in[6];
    const float* Wv   = (const float*)d_in[7];
    const float* bv   = (const float*)d_in[8];
    const float* Wo   = (const float*)d_in[9];
    const float* bo   = (const float*)d_in[10];
    const float* W1   = (const float*)d_in[11];
    const float* b1   = (const float*)d_in[12];
    const float* W2   = (const float*)d_in[13];
    const float* b2   = (const float*)d_in[14];
    const float* n1s  = (const float*)d_in[15];
    const float* n1b  = (const float*)d_in[16];
    const float* n2s  = (const float*)d_in[17];
    const float* n2b  = (const float*)d_in[18];
    float* outp = (float*)d_out;

    float *xp, *xpT, *qkv, *att, *samp, *a, *x, *xT, *hbuf, *fbuf;
    float *wq, *bq, *wo, *w1, *w2;
    cudaGetSymbolAddress((void**)&xp,   g_xp);
    cudaGetSymbolAddress((void**)&xpT,  g_xpT);
    cudaGetSymbolAddress((void**)&qkv,  g_qkv);
    cudaGetSymbolAddress((void**)&att,  g_att);
    cudaGetSymbolAddress((void**)&samp, g_samp);
    cudaGetSymbolAddress((void**)&a,    g_a);
    cudaGetSymbolAddress((void**)&x,    g_x);
    cudaGetSymbolAddress((void**)&xT,   g_xT);
    cudaGetSymbolAddress((void**)&hbuf, g_h);
    cudaGetSymbolAddress((void**)&fbuf, g_f);
    cudaGetSymbolAddress((void**)&wq,   g_wq);
    cudaGetSymbolAddress((void**)&bq,   g_bq);
    cudaGetSymbolAddress((void**)&wo,   g_wo);
    cudaGetSymbolAddress((void**)&w1,   g_w1);
    cudaGetSymbolAddress((void**)&w2,   g_w2);

    cudaFuncSetAttribute(tf32gemm_kernel,
                         cudaFuncAttributeMaxDynamicSharedMemorySize, GEMM_SMEM);

    // ---- weight prep (cheap; once per call) ----
    {
        const int nq = NL_ * C_ * NQKV;
        pack_qkv_kernel<<<(nq + 255) / 256, 256>>>(Wv, Woff, Wat, bv, boff, bat, wq, bq);
        const int n_wo = NL_ * C_ * C_ / 4;
        round_kernel<<<(n_wo + 255) / 256, 256>>>(Wo, wo, n_wo);
        const int n_w1 = NL_ * C_ * FF_ / 4;
        round_kernel<<<(n_w1 + 255) / 256, 256>>>(W1, w1, n_w1);
        const int n_w2 = NL_ * FF_ * C_ / 4;
        round_kernel<<<(n_w2 + 255) / 256, 256>>>(W2, w2, n_w2);
    }

    const int n4 = M_ * C_ / 4;
    const dim3 gQKV(NQKV / BN, M_ / BM);   // (5, 340)
    const dim3 gN256(2, M_ / BM);
    const dim3 gN1024(8, M_ / BM);

    for (int i = 0; i < NL_; i++) {
        const float* xin = (i == 0) ? src : x;
        // xp = x + pos (exact + rounded)
        add_kernel<<<(n4 + 255) / 256, 256>>>(xin, pos, xp, xpT, n4);
        // fused qkv = xpT @ [Wv|Woff|Wat] + [bv|boff|bat]
        tf32gemm_kernel<<<gQKV, 256, GEMM_SMEM>>>(xpT, wq + (size_t)i * C_ * NQKV,
                                                  bq + (size_t)i * NQKV, qkv, NQKV, C_, 0, 0);
        softmax16_kernel<<<(M_ * 8 + 255) / 256, 256>>>(qkv, att, M_ * 8);
        deform_sample_kernel<<<M_, 256>>>(qkv, att, ref, samp);
        // a = samp @ Wo + bo
        tf32gemm_kernel<<<gN256, 256, GEMM_SMEM>>>(samp, wo + (size_t)i * C_ * C_,
                                                   bo + (size_t)i * C_, a, 256, C_, 0, 0);
        // x = LN(xp + a)  (+ rounded copy for W1)
        ln_fused_kernel<<<M_ / 8, 256>>>(xp, a, n1s + (size_t)i * C_, n1b + (size_t)i * C_, x, xT);
        // h = round(relu(xT @ W1 + b1))
        tf32gemm_kernel<<<gN1024, 256, GEMM_SMEM>>>(xT, w1 + (size_t)i * C_ * FF_,
                                                    b1 + (size_t)i * FF_, hbuf, FF_, C_, 1, 1);
        // f = h @ W2 + b2
        tf32gemm_kernel<<<gN256, 256, GEMM_SMEM>>>(hbuf, w2 + (size_t)i * FF_ * C_,
                                                   b2 + (size_t)i * C_, fbuf, 256, FF_, 0, 0);
        // x = LN(x + f)
        float* lnout = (i == NL_ - 1) ? outp : x;
        ln_fused_kernel<<<M_ / 8, 256>>>(x, fbuf, n2s + (size_t)i * C_, n2b + (size_t)i * C_,
                                         lnout, (float*)nullptr);
    }
    (void)in_sizes; (void)n_in; (void)out_size;
}